// round 15
// baseline (speedup 1.0000x reference)
#include <cuda_runtime.h>
#include <cuda_fp16.h>

// Problem constants (capacities for static scratch; runtime sizes used in loops)
#define NNODES 150000
#define MAXE   2000000
#define EMB4   32          // 128 floats = 32 float4 per node row
#define EMBH   32          // 128 halfs  = 32 uint2 per node row
#define SCANB  1024        // scan block size
#define MAXB   16384
#define PBLOCKS 592        // persistent grid: 4 blocks/SM x 148 SMs (co-resident)
#define PTHREADS 256

// ---------------- static device scratch (sanctioned workaround) -------------
__device__ uint2  g_f0[NNODES * EMBH];   // layer 0 fp16 (gather source)
__device__ uint2  g_f1[NNODES * EMBH];   // layer 1 fp16
__device__ uint2  g_f2[NNODES * EMBH];   // layer 2 fp16
__device__ uint2  g_f3[NNODES * EMBH];   // layer 3 fp16 (only sampled rows)
__device__ int    g_cnt[NNODES];
__device__ int    g_rowptr[NNODES + 1];
__device__ int    g_cursor[NNODES];
__device__ int2   g_edge[MAXE];          // fused CSR {col, val-bits}
__device__ int    g_partials[512];
__device__ int    g_bar_count = 0;       // software grid barrier
__device__ volatile int g_bar_gen = 0;

// ---------------- fp16 helpers ----------------------------------------------

__device__ __forceinline__ uint2 f4_to_h8(float4 a) {
    __half2 lo = __floats2half2_rn(a.x, a.y);
    __half2 hi = __floats2half2_rn(a.z, a.w);
    uint2 o;
    o.x = *reinterpret_cast<unsigned*>(&lo);
    o.y = *reinterpret_cast<unsigned*>(&hi);
    return o;
}

__device__ __forceinline__ void fma_h8(float4& acc, float v, uint2 h) {
    float2 lo = __half22float2(*reinterpret_cast<__half2*>(&h.x));
    float2 hi = __half22float2(*reinterpret_cast<__half2*>(&h.y));
    acc.x = fmaf(v, lo.x, acc.x);
    acc.y = fmaf(v, lo.y, acc.y);
    acc.z = fmaf(v, hi.x, acc.z);
    acc.w = fmaf(v, hi.y, acc.w);
}

// ---------------- front end (R14-proven, unchanged) ---------------------------

__global__ void k_zero(int n) {
    int i = blockIdx.x * blockDim.x + threadIdx.x;
    if (i < n) g_cnt[i] = 0;
}

// FUSED init + hist
__global__ void k_init_hist(const float4* __restrict__ uE, const float4* __restrict__ iE,
                            const int* __restrict__ Lrow,
                            int userNum, int n, int e) {
    int i = blockIdx.x * blockDim.x + threadIdx.x;
    int total = n * EMB4;
    if (i < total) {
        int node = i >> 5;
        float4 a = (node < userNum) ? uE[i] : iE[i - userNum * EMB4];
        g_f0[i] = f4_to_h8(a);
    }
    if (i < e) atomicAdd(&g_cnt[Lrow[i]], 1);
}

__global__ void k_block_sums(int n) {
    __shared__ int sh[SCANB];
    int gid = blockIdx.x * SCANB + threadIdx.x;
    sh[threadIdx.x] = (gid < n) ? g_cnt[gid] : 0;
    __syncthreads();
    for (int off = SCANB / 2; off > 0; off >>= 1) {
        if (threadIdx.x < off) sh[threadIdx.x] += sh[threadIdx.x + off];
        __syncthreads();
    }
    if (threadIdx.x == 0) g_partials[blockIdx.x] = sh[0];
}

__global__ void k_scan_apply(int nb, int n) {
    __shared__ int sh[SCANB];
    __shared__ int red_off[32], red_tot[32];
    __shared__ int s_off, s_tot;
    int t = threadIdx.x;

    int p  = (t < nb) ? g_partials[t] : 0;
    int po = (t < (int)blockIdx.x) ? p : 0;
    #pragma unroll
    for (int o = 16; o > 0; o >>= 1) {
        po += __shfl_down_sync(0xffffffffu, po, o);
        p  += __shfl_down_sync(0xffffffffu, p,  o);
    }
    if ((t & 31) == 0) { red_off[t >> 5] = po; red_tot[t >> 5] = p; }
    __syncthreads();
    if (t < 32) {
        int nw = SCANB >> 5;
        int a = (t < nw) ? red_off[t] : 0;
        int b = (t < nw) ? red_tot[t] : 0;
        #pragma unroll
        for (int o = 16; o > 0; o >>= 1) {
            a += __shfl_down_sync(0xffffffffu, a, o);
            b += __shfl_down_sync(0xffffffffu, b, o);
        }
        if (t == 0) { s_off = a; s_tot = b; }
    }
    __syncthreads();

    int gid = blockIdx.x * SCANB + t;
    int v = (gid < n) ? g_cnt[gid] : 0;
    sh[t] = v;
    __syncthreads();
    for (int off = 1; off < SCANB; off <<= 1) {
        int tv = (t >= off) ? sh[t - off] : 0;
        __syncthreads();
        sh[t] += tv;
        __syncthreads();
    }
    if (gid < n) {
        int excl = sh[t] - v + s_off;
        g_rowptr[gid] = excl;
        g_cursor[gid] = excl;
    }
    if (blockIdx.x == 0 && t == 0) g_rowptr[n] = s_tot;
}

__global__ void k_fill(const int* __restrict__ row, const int* __restrict__ col,
                       const float* __restrict__ val, int e) {
    int i = blockIdx.x * blockDim.x + threadIdx.x;
    if (i < e) {
        int r = row[i];
        int p = atomicAdd(&g_cursor[r], 1);
        g_edge[p] = make_int2(col[i], __float_as_int(val[i]));
    }
}

// ---------------- persistent fused back-end -----------------------------------

// software grid barrier: count + generation, volatile spin.
__device__ __forceinline__ void grid_barrier(int nblocks) {
    __syncthreads();
    if (threadIdx.x == 0) {
        __threadfence();                      // make this block's writes visible
        int gen = g_bar_gen;                  // read BEFORE arriving
        if (atomicAdd(&g_bar_count, 1) == nblocks - 1) {
            g_bar_count = 0;
            __threadfence();
            g_bar_gen = gen + 1;              // release
        } else {
            while (g_bar_gen == gen) { }      // volatile spin
        }
        __threadfence();                      // acquire
    }
    __syncthreads();
}

// gather core: NOTE no const/__restrict__ on hin — prevents LDG.CI (incoherent
// path would not observe cross-SM writes made earlier in this same launch).
__device__ __forceinline__ float4 row_gather_p(uint2* hin, int s, int e, int lane) {
    float4 acc = make_float4(0.f, 0.f, 0.f, 0.f);
    for (int base = s; base < e; base += 32) {
        int idx = base + lane;
        int2 ed = (idx < e) ? g_edge[idx] : make_int2(0, 0);
        int m = min(32, e - base);
        #pragma unroll 4
        for (int j = 0; j < m; j++) {
            int   cj = __shfl_sync(0xffffffffu, ed.x, j);
            float vj = __shfl_sync(0xffffffffu, __int_as_float(ed.y), j);
            fma_h8(acc, vj, hin[cj * EMBH + lane]);
        }
    }
    return acc;
}

__global__ void __launch_bounds__(PTHREADS, 4)
k_backend(const float4* __restrict__ uE, const float4* __restrict__ iE,
          const int* __restrict__ uIdx, const int* __restrict__ vIdx,
          int userNum, int n, int B, float* __restrict__ out) {
    int gw   = (blockIdx.x * blockDim.x + threadIdx.x) >> 5;
    int lane = threadIdx.x & 31;
    const int NW = (PBLOCKS * PTHREADS) >> 5;   // 4736 warps

    // layer 1: g_f0 -> g_f1
    for (int w = gw; w < n; w += NW) {
        float4 acc = row_gather_p(g_f0, g_rowptr[w], g_rowptr[w + 1], lane);
        g_f1[w * EMBH + lane] = f4_to_h8(acc);
    }
    grid_barrier(PBLOCKS);

    // layer 2: g_f1 -> g_f2
    for (int w = gw; w < n; w += NW) {
        float4 acc = row_gather_p(g_f1, g_rowptr[w], g_rowptr[w + 1], lane);
        g_f2[w * EMBH + lane] = f4_to_h8(acc);
    }
    grid_barrier(PBLOCKS);

    // layer 3 restricted to sampled rows (duplicates write identical values)
    for (int w = gw; w < 2 * B; w += NW) {
        int r = (w < B) ? uIdx[w] : (vIdx[w - B] + userNum);
        float4 acc = row_gather_p(g_f2, g_rowptr[r], g_rowptr[r + 1], lane);
        g_f3[r * EMBH + lane] = f4_to_h8(acc);
    }
    grid_barrier(PBLOCKS);

    // final dot
    for (int w = gw; w < B; w += NW) {
        int u  = uIdx[w];
        int vi = vIdx[w];
        int v  = vi + userNum;
        int ubh = u * EMBH + lane;
        int vbh = v * EMBH + lane;

        float4 su = uE[u * EMB4 + lane];
        float4 sv = iE[vi * EMB4 + lane];
        fma_h8(su, 1.f, g_f1[ubh]);
        fma_h8(su, 1.f, g_f2[ubh]);
        fma_h8(su, 1.f, g_f3[ubh]);
        fma_h8(sv, 1.f, g_f1[vbh]);
        fma_h8(sv, 1.f, g_f2[vbh]);
        fma_h8(sv, 1.f, g_f3[vbh]);

        float d = su.x * sv.x + su.y * sv.y + su.z * sv.z + su.w * sv.w;
        #pragma unroll
        for (int off = 16; off > 0; off >>= 1)
            d += __shfl_xor_sync(0xffffffffu, d, off);

        if (lane == 0) out[w] = d * 0.0625f;   // (1/4)*(1/4)
    }
}

// ---------------- launch ----------------------------------------------------

extern "C" void kernel_launch(void* const* d_in, const int* in_sizes, int n_in,
                              void* d_out, int out_size) {
    const float4* uE   = (const float4*)d_in[0];
    const float4* iE   = (const float4*)d_in[1];
    const float*  Lval = (const float*)d_in[2];
    const int*    Lrow = (const int*)d_in[3];
    const int*    Lcol = (const int*)d_in[4];
    const int*    uIdx = (const int*)d_in[5];
    const int*    vIdx = (const int*)d_in[6];
    float*        out  = (float*)d_out;

    int userNum = in_sizes[0] / 128;
    int itemNum = in_sizes[1] / 128;
    int n = userNum + itemNum;
    if (n > NNODES) n = NNODES;
    int e = in_sizes[2];
    if (e > MAXE) e = MAXE;
    int B = in_sizes[5];
    if (B > MAXB) B = MAXB;

    int nb = (n + SCANB - 1) / SCANB;

    k_zero      <<<(n + 255) / 256, 256>>>(n);                                   // 0
    k_init_hist <<<(n * EMB4 + 255) / 256, 256>>>(uE, iE, Lrow, userNum, n, e);  // 1
    k_block_sums<<<nb, SCANB>>>(n);                                              // 2
    k_scan_apply<<<nb, SCANB>>>(nb, n);                                          // 3
    k_fill      <<<(e + 255) / 256, 256>>>(Lrow, Lcol, Lval, e);                 // 4
    k_backend   <<<PBLOCKS, PTHREADS>>>(uE, iE, uIdx, vIdx, userNum, n, B, out); // 5 (fused)
}

// round 16
// speedup vs baseline: 1.1435x; 1.1435x over previous
#include <cuda_runtime.h>
#include <cuda_fp16.h>

// Problem constants (capacities for static scratch; runtime sizes used in loops)
#define NNODES 150000
#define MAXE   2000000
#define EMB4   32          // 128 floats = 32 float4 per node row
#define EMBH   32          // 128 halfs  = 32 uint2 per node row
#define SCANB  1024        // scan block size
#define MAXB   16384

// ---------------- static device scratch (sanctioned workaround) -------------
__device__ uint2  g_f0[NNODES * EMBH];   // layer 0 fp16 (gather source)
__device__ uint2  g_f1[NNODES * EMBH];   // layer 1 fp16
__device__ uint2  g_f2[NNODES * EMBH];   // layer 2 fp16
__device__ uint2  g_f3[NNODES * EMBH];   // layer 3 fp16 (only sampled rows)
__device__ int    g_cnt[NNODES];
__device__ int    g_rowptr[NNODES + 1];
__device__ int    g_cursor[NNODES];
__device__ int2   g_edge[MAXE];          // fused CSR {col, val-bits}
__device__ int    g_partials[512];

__device__ __forceinline__ uint2* fp16_buf(int i) {
    return (i == 0) ? g_f0 : (i == 1) ? g_f1 : (i == 2) ? g_f2 : g_f3;
}

// ---------------- fp16 helpers ----------------------------------------------

__device__ __forceinline__ uint2 f4_to_h8(float4 a) {
    __half2 lo = __floats2half2_rn(a.x, a.y);
    __half2 hi = __floats2half2_rn(a.z, a.w);
    uint2 o;
    o.x = *reinterpret_cast<unsigned*>(&lo);
    o.y = *reinterpret_cast<unsigned*>(&hi);
    return o;
}

__device__ __forceinline__ void fma_h8(float4& acc, float v, uint2 h) {
    float2 lo = __half22float2(*reinterpret_cast<__half2*>(&h.x));
    float2 hi = __half22float2(*reinterpret_cast<__half2*>(&h.y));
    acc.x = fmaf(v, lo.x, acc.x);
    acc.y = fmaf(v, lo.y, acc.y);
    acc.z = fmaf(v, hi.x, acc.z);
    acc.w = fmaf(v, hi.y, acc.w);
}

// ---------------- front end ----------------------------------------------------

__global__ void k_zero(int n) {
    int i = blockIdx.x * blockDim.x + threadIdx.x;
    if (i < n) g_cnt[i] = 0;
}

// FUSED init + hist (R14-proven)
__global__ void k_init_hist(const float4* __restrict__ uE, const float4* __restrict__ iE,
                            const int* __restrict__ Lrow,
                            int userNum, int n, int e) {
    int i = blockIdx.x * blockDim.x + threadIdx.x;
    int total = n * EMB4;
    if (i < total) {
        int node = i >> 5;
        float4 a = (node < userNum) ? uE[i] : iE[i - userNum * EMB4];
        g_f0[i] = f4_to_h8(a);
    }
    if (i < e) atomicAdd(&g_cnt[Lrow[i]], 1);
}

__global__ void k_block_sums(int n) {
    __shared__ int sh[SCANB];
    int gid = blockIdx.x * SCANB + threadIdx.x;
    sh[threadIdx.x] = (gid < n) ? g_cnt[gid] : 0;
    __syncthreads();
    for (int off = SCANB / 2; off > 0; off >>= 1) {
        if (threadIdx.x < off) sh[threadIdx.x] += sh[threadIdx.x + off];
        __syncthreads();
    }
    if (threadIdx.x == 0) g_partials[blockIdx.x] = sh[0];
}

// fused partial-offset + per-block exclusive scan -> g_rowptr, g_cursor
__global__ void k_scan_apply(int nb, int n) {
    __shared__ int sh[SCANB];
    __shared__ int red_off[32], red_tot[32];
    __shared__ int s_off, s_tot;
    int t = threadIdx.x;

    int p  = (t < nb) ? g_partials[t] : 0;
    int po = (t < (int)blockIdx.x) ? p : 0;
    #pragma unroll
    for (int o = 16; o > 0; o >>= 1) {
        po += __shfl_down_sync(0xffffffffu, po, o);
        p  += __shfl_down_sync(0xffffffffu, p,  o);
    }
    if ((t & 31) == 0) { red_off[t >> 5] = po; red_tot[t >> 5] = p; }
    __syncthreads();
    if (t < 32) {
        int nw = SCANB >> 5;
        int a = (t < nw) ? red_off[t] : 0;
        int b = (t < nw) ? red_tot[t] : 0;
        #pragma unroll
        for (int o = 16; o > 0; o >>= 1) {
            a += __shfl_down_sync(0xffffffffu, a, o);
            b += __shfl_down_sync(0xffffffffu, b, o);
        }
        if (t == 0) { s_off = a; s_tot = b; }
    }
    __syncthreads();

    int gid = blockIdx.x * SCANB + t;
    int v = (gid < n) ? g_cnt[gid] : 0;
    sh[t] = v;
    __syncthreads();
    for (int off = 1; off < SCANB; off <<= 1) {
        int tv = (t >= off) ? sh[t - off] : 0;
        __syncthreads();
        sh[t] += tv;
        __syncthreads();
    }
    if (gid < n) {
        int excl = sh[t] - v + s_off;
        g_rowptr[gid] = excl;
        g_cursor[gid] = excl;
    }
    if (blockIdx.x == 0 && t == 0) g_rowptr[n] = s_tot;
}

// counting-sort edges into fused int2 CSR slots.
// 4 INDEPENDENT edge chains per thread (grid-stride) -> 4 outstanding atomics
// per thread, covering ATOMG latency (R6 profile: issue=5%, L2=55% => latency-bound).
__global__ void k_fill(const int* __restrict__ row, const int* __restrict__ col,
                       const float* __restrict__ val, int e, int stride) {
    int tid = blockIdx.x * blockDim.x + threadIdx.x;
    int i0 = tid;
    int i1 = tid + stride;
    int i2 = tid + 2 * stride;
    int i3 = tid + 3 * stride;

    int r0 = 0, r1 = 0, r2 = 0, r3 = 0;
    int c0 = 0, c1 = 0, c2 = 0, c3 = 0;
    float v0 = 0.f, v1 = 0.f, v2 = 0.f, v3 = 0.f;
    if (i0 < e) { r0 = row[i0]; c0 = col[i0]; v0 = val[i0]; }
    if (i1 < e) { r1 = row[i1]; c1 = col[i1]; v1 = val[i1]; }
    if (i2 < e) { r2 = row[i2]; c2 = col[i2]; v2 = val[i2]; }
    if (i3 < e) { r3 = row[i3]; c3 = col[i3]; v3 = val[i3]; }

    int p0 = 0, p1 = 0, p2 = 0, p3 = 0;
    if (i0 < e) p0 = atomicAdd(&g_cursor[r0], 1);
    if (i1 < e) p1 = atomicAdd(&g_cursor[r1], 1);
    if (i2 < e) p2 = atomicAdd(&g_cursor[r2], 1);
    if (i3 < e) p3 = atomicAdd(&g_cursor[r3], 1);

    if (i0 < e) g_edge[p0] = make_int2(c0, __float_as_int(v0));
    if (i1 < e) g_edge[p1] = make_int2(c1, __float_as_int(v1));
    if (i2 < e) g_edge[p2] = make_int2(c2, __float_as_int(v2));
    if (i3 < e) g_edge[p3] = make_int2(c3, __float_as_int(v3));
}

// ---------------- SpMM (warp per row, fp16 gather / fp32 accum) ---------------

__device__ __forceinline__ float4 row_gather(const uint2* __restrict__ hin,
                                             int s, int e, int lane) {
    float4 acc = make_float4(0.f, 0.f, 0.f, 0.f);
    for (int base = s; base < e; base += 32) {
        int idx = base + lane;
        int2 ed = (idx < e) ? g_edge[idx] : make_int2(0, 0);
        int m = min(32, e - base);
        #pragma unroll 4
        for (int j = 0; j < m; j++) {
            int   cj = __shfl_sync(0xffffffffu, ed.x, j);
            float vj = __shfl_sync(0xffffffffu, __int_as_float(ed.y), j);
            fma_h8(acc, vj, hin[cj * EMBH + lane]);
        }
    }
    return acc;
}

__global__ void k_spmm(int stage, int n) {
    const uint2* __restrict__ hin = fp16_buf(stage);
    uint2* hout = fp16_buf(stage + 1);
    int w    = (blockIdx.x * blockDim.x + threadIdx.x) >> 5;
    int lane = threadIdx.x & 31;
    if (w >= n) return;
    float4 acc = row_gather(hin, g_rowptr[w], g_rowptr[w + 1], lane);
    hout[w * EMBH + lane] = f4_to_h8(acc);
}

// layer-3 SpMM over sampled rows directly (duplicates recompute identical
// values and race benignly on identical writes — deterministic)
__global__ void k_spmm3(const int* __restrict__ uIdx, const int* __restrict__ vIdx,
                        int userNum, int B) {
    int w    = (blockIdx.x * blockDim.x + threadIdx.x) >> 5;
    int lane = threadIdx.x & 31;
    if (w >= 2 * B) return;
    int r = (w < B) ? uIdx[w] : (vIdx[w - B] + userNum);
    float4 acc = row_gather(g_f2, g_rowptr[r], g_rowptr[r + 1], lane);
    g_f3[r * EMBH + lane] = f4_to_h8(acc);
}

// ---------------- final dot ---------------------------------------------------

__global__ void k_dot(const float4* __restrict__ uE, const float4* __restrict__ iE,
                      const int* __restrict__ uIdx, const int* __restrict__ vIdx,
                      int userNum, int B, float* __restrict__ out) {
    int w    = (blockIdx.x * blockDim.x + threadIdx.x) >> 5;
    int lane = threadIdx.x & 31;
    if (w >= B) return;

    int u  = uIdx[w];
    int vi = vIdx[w];
    int v  = vi + userNum;
    int ubh = u * EMBH + lane;
    int vbh = v * EMBH + lane;

    float4 su = uE[u * EMB4 + lane];           // layer 0 fp32 from input
    float4 sv = iE[vi * EMB4 + lane];
    fma_h8(su, 1.f, g_f1[ubh]);
    fma_h8(su, 1.f, g_f2[ubh]);
    fma_h8(su, 1.f, g_f3[ubh]);
    fma_h8(sv, 1.f, g_f1[vbh]);
    fma_h8(sv, 1.f, g_f2[vbh]);
    fma_h8(sv, 1.f, g_f3[vbh]);

    float d = su.x * sv.x + su.y * sv.y + su.z * sv.z + su.w * sv.w;
    #pragma unroll
    for (int off = 16; off > 0; off >>= 1)
        d += __shfl_xor_sync(0xffffffffu, d, off);

    if (lane == 0) out[w] = d * 0.0625f;   // (1/4)*(1/4) for the layer average
}

// ---------------- launch ----------------------------------------------------

extern "C" void kernel_launch(void* const* d_in, const int* in_sizes, int n_in,
                              void* d_out, int out_size) {
    const float4* uE   = (const float4*)d_in[0];
    const float4* iE   = (const float4*)d_in[1];
    const float*  Lval = (const float*)d_in[2];
    const int*    Lrow = (const int*)d_in[3];
    const int*    Lcol = (const int*)d_in[4];
    const int*    uIdx = (const int*)d_in[5];
    const int*    vIdx = (const int*)d_in[6];
    float*        out  = (float*)d_out;

    int userNum = in_sizes[0] / 128;
    int itemNum = in_sizes[1] / 128;
    int n = userNum + itemNum;
    if (n > NNODES) n = NNODES;
    int e = in_sizes[2];
    if (e > MAXE) e = MAXE;
    int B = in_sizes[5];
    if (B > MAXB) B = MAXB;

    int nb = (n + SCANB - 1) / SCANB;
    int spmm_blocks = (n + 7) / 8;

    // fill: 4 edges per thread, grid-stride spacing keeps loads coalesced
    int fill_threads = (e + 3) / 4;
    int fill_blocks  = (fill_threads + 255) / 256;
    int fill_stride  = fill_blocks * 256;

    k_zero      <<<(n + 255) / 256, 256>>>(n);                                   // 0
    k_init_hist <<<(n * EMB4 + 255) / 256, 256>>>(uE, iE, Lrow, userNum, n, e);  // 1
    k_block_sums<<<nb, SCANB>>>(n);                                              // 2
    k_scan_apply<<<nb, SCANB>>>(nb, n);                                          // 3
    k_fill      <<<fill_blocks, 256>>>(Lrow, Lcol, Lval, e, fill_stride);        // 4
    k_spmm      <<<spmm_blocks, 256>>>(0, n);                                    // 5
    k_spmm      <<<spmm_blocks, 256>>>(1, n);                                    // 6
    k_spmm3     <<<(2 * B + 7) / 8, 256>>>(uIdx, vIdx, userNum, B);              // 7
    k_dot       <<<(B + 7) / 8, 256>>>(uE, iE, uIdx, vIdx, userNum, B, out);     // 8
}

// round 17
// speedup vs baseline: 1.1626x; 1.0167x over previous
#include <cuda_runtime.h>
#include <cuda_fp16.h>

// Problem constants (capacities for static scratch; runtime sizes used in loops)
#define NNODES 150000
#define MAXE   2000000
#define EMB4   32          // 128 floats = 32 float4 per node row
#define EMBH   32          // 128 halfs  = 32 uint2 per node row
#define SCANB  1024        // scan block size
#define MAXB   16384

// ---------------- static device scratch (sanctioned workaround) -------------
// NOTE: g_cnt relies on (a) CUDA zero-initialization of __device__ globals at
// module load for the FIRST execution, and (b) k_fill re-zeroing it at the end
// of EVERY execution (after both scan kernels have consumed it). Stream order
// guarantees the invariant across correctness run, calibration and replays.
__device__ uint2  g_f0[NNODES * EMBH];   // layer 0 fp16 (gather source)
__device__ uint2  g_f1[NNODES * EMBH];   // layer 1 fp16
__device__ uint2  g_f2[NNODES * EMBH];   // layer 2 fp16
__device__ uint2  g_f3[NNODES * EMBH];   // layer 3 fp16 (only sampled rows)
__device__ int    g_cnt[NNODES];         // zero at entry of every execution
__device__ int    g_rowptr[NNODES + 1];
__device__ int    g_cursor[NNODES];
__device__ int2   g_edge[MAXE];          // fused CSR {col, val-bits}
__device__ int    g_partials[512];

__device__ __forceinline__ uint2* fp16_buf(int i) {
    return (i == 0) ? g_f0 : (i == 1) ? g_f1 : (i == 2) ? g_f2 : g_f3;
}

// ---------------- fp16 helpers ----------------------------------------------

__device__ __forceinline__ uint2 f4_to_h8(float4 a) {
    __half2 lo = __floats2half2_rn(a.x, a.y);
    __half2 hi = __floats2half2_rn(a.z, a.w);
    uint2 o;
    o.x = *reinterpret_cast<unsigned*>(&lo);
    o.y = *reinterpret_cast<unsigned*>(&hi);
    return o;
}

__device__ __forceinline__ void fma_h8(float4& acc, float v, uint2 h) {
    float2 lo = __half22float2(*reinterpret_cast<__half2*>(&h.x));
    float2 hi = __half22float2(*reinterpret_cast<__half2*>(&h.y));
    acc.x = fmaf(v, lo.x, acc.x);
    acc.y = fmaf(v, lo.y, acc.y);
    acc.z = fmaf(v, hi.x, acc.z);
    acc.w = fmaf(v, hi.y, acc.w);
}

// ---------------- front end ----------------------------------------------------

// FUSED init + hist (R14-proven). g_cnt is guaranteed zero at entry (see note).
__global__ void k_init_hist(const float4* __restrict__ uE, const float4* __restrict__ iE,
                            const int* __restrict__ Lrow,
                            int userNum, int n, int e) {
    int i = blockIdx.x * blockDim.x + threadIdx.x;
    int total = n * EMB4;
    if (i < total) {
        int node = i >> 5;
        float4 a = (node < userNum) ? uE[i] : iE[i - userNum * EMB4];
        g_f0[i] = f4_to_h8(a);
    }
    if (i < e) atomicAdd(&g_cnt[Lrow[i]], 1);
}

__global__ void k_block_sums(int n) {
    __shared__ int sh[SCANB];
    int gid = blockIdx.x * SCANB + threadIdx.x;
    sh[threadIdx.x] = (gid < n) ? g_cnt[gid] : 0;
    __syncthreads();
    for (int off = SCANB / 2; off > 0; off >>= 1) {
        if (threadIdx.x < off) sh[threadIdx.x] += sh[threadIdx.x + off];
        __syncthreads();
    }
    if (threadIdx.x == 0) g_partials[blockIdx.x] = sh[0];
}

// fused partial-offset + per-block exclusive scan -> g_rowptr, g_cursor
__global__ void k_scan_apply(int nb, int n) {
    __shared__ int sh[SCANB];
    __shared__ int red_off[32], red_tot[32];
    __shared__ int s_off, s_tot;
    int t = threadIdx.x;

    int p  = (t < nb) ? g_partials[t] : 0;
    int po = (t < (int)blockIdx.x) ? p : 0;
    #pragma unroll
    for (int o = 16; o > 0; o >>= 1) {
        po += __shfl_down_sync(0xffffffffu, po, o);
        p  += __shfl_down_sync(0xffffffffu, p,  o);
    }
    if ((t & 31) == 0) { red_off[t >> 5] = po; red_tot[t >> 5] = p; }
    __syncthreads();
    if (t < 32) {
        int nw = SCANB >> 5;
        int a = (t < nw) ? red_off[t] : 0;
        int b = (t < nw) ? red_tot[t] : 0;
        #pragma unroll
        for (int o = 16; o > 0; o >>= 1) {
            a += __shfl_down_sync(0xffffffffu, a, o);
            b += __shfl_down_sync(0xffffffffu, b, o);
        }
        if (t == 0) { s_off = a; s_tot = b; }
    }
    __syncthreads();

    int gid = blockIdx.x * SCANB + t;
    int v = (gid < n) ? g_cnt[gid] : 0;
    sh[t] = v;
    __syncthreads();
    for (int off = 1; off < SCANB; off <<= 1) {
        int tv = (t >= off) ? sh[t - off] : 0;
        __syncthreads();
        sh[t] += tv;
        __syncthreads();
    }
    if (gid < n) {
        int excl = sh[t] - v + s_off;
        g_rowptr[gid] = excl;
        g_cursor[gid] = excl;
    }
    if (blockIdx.x == 0 && t == 0) g_rowptr[n] = s_tot;
}

// counting-sort edges into fused int2 CSR slots; ALSO re-zeros g_cnt for the
// next execution (both scan kernels already consumed it — stream order).
__global__ void k_fill(const int* __restrict__ row, const int* __restrict__ col,
                       const float* __restrict__ val, int e, int n) {
    int i = blockIdx.x * blockDim.x + threadIdx.x;
    if (i < e) {
        int r = row[i];
        int p = atomicAdd(&g_cursor[r], 1);
        g_edge[p] = make_int2(col[i], __float_as_int(val[i]));
    }
    if (i < n) g_cnt[i] = 0;   // self-cleaning invariant (replaces k_zero launch)
}

// ---------------- SpMM (warp per row, fp16 gather / fp32 accum) ---------------

__device__ __forceinline__ float4 row_gather(const uint2* __restrict__ hin,
                                             int s, int e, int lane) {
    float4 acc = make_float4(0.f, 0.f, 0.f, 0.f);
    for (int base = s; base < e; base += 32) {
        int idx = base + lane;
        int2 ed = (idx < e) ? g_edge[idx] : make_int2(0, 0);
        int m = min(32, e - base);
        #pragma unroll 4
        for (int j = 0; j < m; j++) {
            int   cj = __shfl_sync(0xffffffffu, ed.x, j);
            float vj = __shfl_sync(0xffffffffu, __int_as_float(ed.y), j);
            fma_h8(acc, vj, hin[cj * EMBH + lane]);
        }
    }
    return acc;
}

__global__ void k_spmm(int stage, int n) {
    const uint2* __restrict__ hin = fp16_buf(stage);
    uint2* hout = fp16_buf(stage + 1);
    int w    = (blockIdx.x * blockDim.x + threadIdx.x) >> 5;
    int lane = threadIdx.x & 31;
    if (w >= n) return;
    float4 acc = row_gather(hin, g_rowptr[w], g_rowptr[w + 1], lane);
    hout[w * EMBH + lane] = f4_to_h8(acc);
}

// layer-3 SpMM over sampled rows directly (duplicates recompute identical
// values and race benignly on identical writes — deterministic)
__global__ void k_spmm3(const int* __restrict__ uIdx, const int* __restrict__ vIdx,
                        int userNum, int B) {
    int w    = (blockIdx.x * blockDim.x + threadIdx.x) >> 5;
    int lane = threadIdx.x & 31;
    if (w >= 2 * B) return;
    int r = (w < B) ? uIdx[w] : (vIdx[w - B] + userNum);
    float4 acc = row_gather(g_f2, g_rowptr[r], g_rowptr[r + 1], lane);
    g_f3[r * EMBH + lane] = f4_to_h8(acc);
}

// ---------------- final dot ---------------------------------------------------

__global__ void k_dot(const float4* __restrict__ uE, const float4* __restrict__ iE,
                      const int* __restrict__ uIdx, const int* __restrict__ vIdx,
                      int userNum, int B, float* __restrict__ out) {
    int w    = (blockIdx.x * blockDim.x + threadIdx.x) >> 5;
    int lane = threadIdx.x & 31;
    if (w >= B) return;

    int u  = uIdx[w];
    int vi = vIdx[w];
    int v  = vi + userNum;
    int ubh = u * EMBH + lane;
    int vbh = v * EMBH + lane;

    float4 su = uE[u * EMB4 + lane];           // layer 0 fp32 from input
    float4 sv = iE[vi * EMB4 + lane];
    fma_h8(su, 1.f, g_f1[ubh]);
    fma_h8(su, 1.f, g_f2[ubh]);
    fma_h8(su, 1.f, g_f3[ubh]);
    fma_h8(sv, 1.f, g_f1[vbh]);
    fma_h8(sv, 1.f, g_f2[vbh]);
    fma_h8(sv, 1.f, g_f3[vbh]);

    float d = su.x * sv.x + su.y * sv.y + su.z * sv.z + su.w * sv.w;
    #pragma unroll
    for (int off = 16; off > 0; off >>= 1)
        d += __shfl_xor_sync(0xffffffffu, d, off);

    if (lane == 0) out[w] = d * 0.0625f;   // (1/4)*(1/4) for the layer average
}

// ---------------- launch ----------------------------------------------------

extern "C" void kernel_launch(void* const* d_in, const int* in_sizes, int n_in,
                              void* d_out, int out_size) {
    const float4* uE   = (const float4*)d_in[0];
    const float4* iE   = (const float4*)d_in[1];
    const float*  Lval = (const float*)d_in[2];
    const int*    Lrow = (const int*)d_in[3];
    const int*    Lcol = (const int*)d_in[4];
    const int*    uIdx = (const int*)d_in[5];
    const int*    vIdx = (const int*)d_in[6];
    float*        out  = (float*)d_out;

    int userNum = in_sizes[0] / 128;
    int itemNum = in_sizes[1] / 128;
    int n = userNum + itemNum;
    if (n > NNODES) n = NNODES;
    int e = in_sizes[2];
    if (e > MAXE) e = MAXE;
    int B = in_sizes[5];
    if (B > MAXB) B = MAXB;

    int nb = (n + SCANB - 1) / SCANB;
    int spmm_blocks = (n + 7) / 8;

    k_init_hist <<<(n * EMB4 + 255) / 256, 256>>>(uE, iE, Lrow, userNum, n, e);  // 0
    k_block_sums<<<nb, SCANB>>>(n);                                              // 1
    k_scan_apply<<<nb, SCANB>>>(nb, n);                                          // 2
    k_fill      <<<(e + 255) / 256, 256>>>(Lrow, Lcol, Lval, e, n);              // 3
    k_spmm      <<<spmm_blocks, 256>>>(0, n);                                    // 4
    k_spmm      <<<spmm_blocks, 256>>>(1, n);                                    // 5
    k_spmm3     <<<(2 * B + 7) / 8, 256>>>(uIdx, vIdx, userNum, B);              // 6
    k_dot       <<<(B + 7) / 8, 256>>>(uE, iE, uIdx, vIdx, userNum, B, out);     // 7
}